// round 4
// baseline (speedup 1.0000x reference)
#include <cuda_runtime.h>

#define WD 512
#define RB 4
#define NBATCH 8
#define ROWF 520
#define RING_ROWS 16
#define RING_STRIDE (2 * WD)            // floats per ring row (I plane then J plane)
#define NCC_BLOCKS 512
#define GRAD_BLOCKS 64
#define TOTAL_BLOCKS (NCC_BLOCKS + GRAD_BLOCKS)
#define RING_FLOATS (RING_ROWS * RING_STRIDE)   // 16384 floats = 64 KB
#define STAGE_FLOATS (RB * 5 * ROWF)            // 10400 floats = 41.6 KB
#define SMEM_BYTES ((RING_FLOATS + STAGE_FLOATS) * 4)   // 107136 B

// [0],[1]: cc sums per channel; [2]: sum dx^2; [3]: sum dy^2
__device__ double g_acc[4];
__device__ unsigned int g_count;

__device__ __forceinline__ void cpa4(float* dst, const float* src) {
    unsigned sa = (unsigned)__cvta_generic_to_shared(dst);
    asm volatile("cp.async.ca.shared.global [%0], [%1], 4;" :: "r"(sa), "l"(src) : "memory");
}
__device__ __forceinline__ void cpa_commit() {
    asm volatile("cp.async.commit_group;" ::: "memory");
}
__device__ __forceinline__ void cpa_wait1() {
    asm volatile("cp.async.wait_group 1;" ::: "memory");
}

__global__ __launch_bounds__(512, 2) void fused_kernel(const float* __restrict__ I,
                                                       const float* __restrict__ J,
                                                       const float* __restrict__ dvf,
                                                       int n_dvf,
                                                       float* __restrict__ out) {
    extern __shared__ __align__(16) float dyn[];
    float* ring  = dyn;                 // [16][2][512]
    float* stage = dyn + RING_FLOATS;   // [RB][5][ROWF]
    __shared__ float red[16];
    __shared__ float red2[16];
    __shared__ bool is_last;

    const int t = threadIdx.x;
    const int blk = blockIdx.x;

    if (blk < NCC_BLOCKS) {
        // ───────────────────────── NCC block ─────────────────────────
        const int img = blk >> 4;       // 16 bands per image, 32 images
        const int band = blk & 15;
        const int r0 = band * 32;
        const size_t base = (size_t)img * (WD * WD);
        const float* __restrict__ Ip = I + base;
        const float* __restrict__ Jp = J + base;

        // issue 4 rows [rlo, rlo+4) into the ring as ONE commit group.
        // thread t owns column t of both planes -> self-produced, self-consumed.
        auto issue4 = [&](int rlo, bool do_issue) {
            if (do_issue) {
#pragma unroll
                for (int k = 0; k < 4; k++) {
                    const int r = rlo + k;
                    const int slot = r & (RING_ROWS - 1);
                    float* dI = ring + slot * RING_STRIDE + t;
                    float* dJ = dI + WD;
                    if ((unsigned)r < (unsigned)WD) {
                        cpa4(dI, Ip + r * WD + t);
                        cpa4(dJ, Jp + r * WD + t);
                    } else {            // halo rows outside the image: zeros
                        *dI = 0.f;
                        *dJ = 0.f;
                    }
                }
            }
            cpa_commit();               // always commit (keeps wait counting fixed)
        };

        // zero the horizontal padding of the staging buffer (cols 0..3, 516..519)
        if (t < 4) {
#pragma unroll
            for (int rr = 0; rr < RB; rr++)
#pragma unroll
                for (int q = 0; q < 5; q++) {
                    float* row = stage + (size_t)(rr * 5 + q) * ROWF;
                    row[t] = 0.0f;
                    row[516 + t] = 0.0f;
                }
        }

        // prime the ring: groups G0..G3 = rows [r0-4, r0+12)
        issue4(r0 - 4, true);
        issue4(r0, true);
        issue4(r0 + 4, true);
        issue4(r0 + 8, true);
        cpa_wait1();                    // G0..G2 complete

        // vertical prime: column sums over rows [r0-4, r0+3] (halo rows are zeros)
        float cs0 = 0.f, cs1 = 0.f, cs2 = 0.f, cs3 = 0.f, cs4 = 0.f;
#pragma unroll
        for (int k = 0; k < 8; k++) {
            const int slot = (r0 - 4 + k) & (RING_ROWS - 1);
            float a = ring[slot * RING_STRIDE + t];
            float b = ring[slot * RING_STRIDE + WD + t];
            cs0 += a; cs1 += b; cs2 += a * a; cs3 += b * b; cs4 += a * b;
        }

        float acc = 0.f;
        const int rsB = t >> 7;         // which of the 4 staged rows
        const int seg = t & 127;        // 4-column run: cols [seg*4, seg*4+4)
        const float inv81 = 1.0f / 81.0f;

        for (int b = 0; b < NBATCH; b++) {
            // guarantees groups up to G(b+2) (rows <= r0+4b+7) have landed
            cpa_wait1();

            // ── phase A: slide vertical sums, stage RB rows of column sums ──
#pragma unroll
            for (int rr = 0; rr < RB; rr++) {
                const int r = r0 + 4 * b + rr;
                const int sa = (r + 4) & (RING_ROWS - 1);
                float a = ring[sa * RING_STRIDE + t];
                float bb = ring[sa * RING_STRIDE + WD + t];
                cs0 += a; cs1 += bb; cs2 += a * a; cs3 += bb * bb; cs4 += a * bb;
                float* rowp = stage + (size_t)(rr * 5) * ROWF + 4 + t;
                rowp[0 * ROWF] = cs0;
                rowp[1 * ROWF] = cs1;
                rowp[2 * ROWF] = cs2;
                rowp[3 * ROWF] = cs3;
                rowp[4 * ROWF] = cs4;
                const int ss = (r - 4) & (RING_ROWS - 1);
                float c = ring[ss * RING_STRIDE + t];
                float d = ring[ss * RING_STRIDE + WD + t];
                cs0 -= c; cs1 -= d; cs2 -= c * c; cs3 -= d * d; cs4 -= c * d;
            }

            // prefetch G(b+4): rows [r0+4b+12, r0+4b+16) — needed at batch b+2.
            // Overwrites G(b) slots, whose last read (sub rows) just happened above.
            issue4(r0 + 4 * b + 12, b + 4 <= 9);

            __syncthreads();            // staged sums ready

            // ── phase B: horizontal 9-sums + cc ──
            float S[5][4];
#pragma unroll
            for (int q = 0; q < 5; q++) {
                const float4* row4 = (const float4*)(stage + (size_t)(rsB * 5 + q) * ROWF);
                float4 A = row4[seg], B = row4[seg + 1], C = row4[seg + 2];
                float s = A.x + A.y + A.z + A.w + B.x + B.y + B.z + B.w + C.x;
                S[q][0] = s;
                s += C.y - A.x; S[q][1] = s;
                s += C.z - A.y; S[q][2] = s;
                s += C.w - A.z; S[q][3] = s;
            }
#pragma unroll
            for (int i = 0; i < 4; i++) {
                float sI = S[0][i], sJ = S[1][i];
                float sII = S[2][i], sJJ = S[3][i], sIJ = S[4][i];
                float cross = sIJ - sI * sJ * inv81;
                float Iv = sII - sI * sI * inv81;
                float Jv = sJJ - sJ * sJ * inv81;
                acc += __fdividef(cross * cross, Iv * Jv + 1e-5f);
            }
            __syncthreads();            // stage free for next phase A
        }

        // block reduction
#pragma unroll
        for (int d = 16; d > 0; d >>= 1) acc += __shfl_down_sync(0xffffffffu, acc, d);
        if ((t & 31) == 0) red[t >> 5] = acc;
        __syncthreads();
        if (t < 32) {
            float v = (t < 16) ? red[t] : 0.f;
#pragma unroll
            for (int d = 8; d > 0; d >>= 1) v += __shfl_down_sync(0xffffffffu, v, d);
            if (t == 0) atomicAdd(&g_acc[img & 1], (double)v);
        }
    } else {
        // ───────────────────────── grad block ─────────────────────────
        float adx = 0.f, ady = 0.f;
        const int gb = blk - NCC_BLOCKS;
        for (int idx = gb * 512 + t; idx < n_dvf; idx += GRAD_BLOCKS * 512) {
            const int hw = idx & 65535;          // position within one 256x256 map
            const float c = dvf[idx];
            if ((hw & 255) != 255) { float d = dvf[idx + 1] - c; adx += d * d; }
            if (hw < 65280)        { float d = dvf[idx + 256] - c; ady += d * d; }
        }
#pragma unroll
        for (int d = 16; d > 0; d >>= 1) {
            adx += __shfl_down_sync(0xffffffffu, adx, d);
            ady += __shfl_down_sync(0xffffffffu, ady, d);
        }
        if ((t & 31) == 0) { red[t >> 5] = adx; red2[t >> 5] = ady; }
        __syncthreads();
        if (t < 32) {
            float x = (t < 16) ? red[t] : 0.f;
            float y = (t < 16) ? red2[t] : 0.f;
#pragma unroll
            for (int d = 8; d > 0; d >>= 1) {
                x += __shfl_down_sync(0xffffffffu, x, d);
                y += __shfl_down_sync(0xffffffffu, y, d);
            }
            if (t == 0) {
                atomicAdd(&g_acc[2], (double)x);
                atomicAdd(&g_acc[3], (double)y);
            }
        }
    }

    // ───────────────── last-block finalize (graph-replay safe) ─────────────────
    __threadfence();
    if (t == 0) {
        unsigned int prev = atomicAdd(&g_count, 1u);
        is_last = (prev == (unsigned int)(TOTAL_BLOCKS - 1));
    }
    __syncthreads();
    if (is_last && t == 0) {
        // ncc = -(m0 + m1)/(C-1), C=2; m_c = sum_c / (B*H*W)
        double ncc = -(g_acc[0] + g_acc[1]) / (16.0 * 512.0 * 512.0);
        // grad = 0.01 * ((mean(dx^2)+mean(dy^2))/2 * 2.0)
        double Nd = 16.0 * 2.0 * 256.0 * 255.0;
        double grad = 0.01 * (g_acc[2] / Nd + g_acc[3] / Nd);
        out[0] = (float)(ncc + grad);
        out[1] = (float)ncc;
        out[2] = (float)grad;
        g_acc[0] = 0.0; g_acc[1] = 0.0; g_acc[2] = 0.0; g_acc[3] = 0.0;
        g_count = 0u;
    }
}

extern "C" void kernel_launch(void* const* d_in, const int* in_sizes, int n_in,
                              void* d_out, int out_size) {
    const float* y_true = (const float*)d_in[0];
    const float* y_pred = (const float*)d_in[1];
    const float* dvf    = (const float*)d_in[2];
    float* out = (float*)d_out;
    const int n_dvf = in_sizes[2];

    cudaFuncSetAttribute(fused_kernel, cudaFuncAttributeMaxDynamicSharedMemorySize,
                         SMEM_BYTES);
    fused_kernel<<<TOTAL_BLOCKS, 512, SMEM_BYTES>>>(y_true, y_pred, dvf, n_dvf, out);
}

// round 6
// speedup vs baseline: 1.0065x; 1.0065x over previous
#include <cuda_runtime.h>

#define WD 512
#define RB 4
#define NBATCH 8
#define ROWF 520            // 4 pad + 512 + 4 pad
#define NCC_BLOCKS 512
#define GRAD_BLOCKS 64
#define TOTAL_BLOCKS (NCC_BLOCKS + GRAD_BLOCKS)
#define STAGE_FLOATS (2 * RB * 5 * ROWF)       // 20800 floats = 83200 B (double buffer)
#define STASH_FLOATS (8 * WD * 2)              // 8192 floats = 32768 B (8-row raw ring)
#define SMEM_BYTES ((STAGE_FLOATS + STASH_FLOATS) * 4)   // 115968 B

// [0],[1]: cc sums per channel; [2]: sum dx^2; [3]: sum dy^2
__device__ double g_acc[4];
__device__ unsigned int g_count;

__global__ __launch_bounds__(512, 2) void fused_kernel(const float* __restrict__ I,
                                                       const float* __restrict__ J,
                                                       const float* __restrict__ dvf,
                                                       int n_dvf,
                                                       float* __restrict__ out) {
    extern __shared__ __align__(16) float dyn[];
    float* stage = dyn;                         // [2][RB][5][ROWF]
    float2* stash = (float2*)(dyn + STAGE_FLOATS);   // [8][WD] float2 (a,b)
    __shared__ float red[16];
    __shared__ float red2[16];
    __shared__ bool is_last;

    const int t = threadIdx.x;
    const int blk = blockIdx.x;

    if (blk < NCC_BLOCKS) {
        // ───────────────────────── NCC block ─────────────────────────
        const int img = blk >> 4;       // 16 bands per image, 32 images
        const int band = blk & 15;
        const int r0 = band * 32;       // multiple of 32 -> r0 & 7 == 0
        const size_t base = (size_t)img * (WD * WD);
        const float* __restrict__ Ip = I + base;
        const float* __restrict__ Jp = J + base;

        // zero the horizontal padding (cols 0..3, 516..519) in BOTH stage buffers
        if (t < 4) {
#pragma unroll
            for (int bu = 0; bu < 2; bu++)
#pragma unroll
                for (int rr = 0; rr < RB; rr++)
#pragma unroll
                    for (int q = 0; q < 5; q++) {
                        float* row = stage + (size_t)(((bu * RB) + rr) * 5 + q) * ROWF;
                        row[t] = 0.0f;
                        row[516 + t] = 0.0f;
                    }
        }

        // prime: column sums over rows [r0-4, r0+3]; stash raw rows in ring.
        // slot(row x) = x & 7; r0 ≡ 0 (mod 8) so slot = (k+4)&7 here.
        float cs0 = 0.f, cs1 = 0.f, cs2 = 0.f, cs3 = 0.f, cs4 = 0.f;
#pragma unroll
        for (int k = 0; k < 8; k++) {
            const int r = r0 - 4 + k;
            float a = 0.f, b = 0.f;
            if (r >= 0) { a = Ip[r * WD + t]; b = Jp[r * WD + t]; }
            stash[((k + 4) & 7) * WD + t] = make_float2(a, b);
            cs0 += a; cs1 += b; cs2 += a * a; cs3 += b * b; cs4 += a * b;
        }

        // phase A: slide vertical sums over RB rows, stage column sums.
        // jpar = (rbase/4) & 1 — makes stash slots compile-time constants.
        auto phaseA = [&](int buf, int rbase, int jpar) {
#pragma unroll
            for (int rr = 0; rr < RB; rr++) {
                const int r = rbase + rr;
                const int slot = (jpar * 4 + rr + 4) & 7;   // == (r+4)&7 == (r-4)&7
                // read sub row (r-4) from stash BEFORE overwriting the slot
                float2 cd = stash[slot * WD + t];
                // load add row (r+4) from global (each row read exactly once)
                float a = 0.f, b = 0.f;
                if (r + 4 < WD) { a = Ip[(r + 4) * WD + t]; b = Jp[(r + 4) * WD + t]; }
                stash[slot * WD + t] = make_float2(a, b);
                cs0 += a; cs1 += b; cs2 += a * a; cs3 += b * b; cs4 += a * b;
                float* rowp = stage + (size_t)((buf * RB + rr) * 5) * ROWF + 4 + t;
                rowp[0 * ROWF] = cs0;
                rowp[1 * ROWF] = cs1;
                rowp[2 * ROWF] = cs2;
                rowp[3 * ROWF] = cs3;
                rowp[4 * ROWF] = cs4;
                cs0 -= cd.x; cs1 -= cd.y;
                cs2 -= cd.x * cd.x; cs3 -= cd.y * cd.y; cs4 -= cd.x * cd.y;
            }
        };

        float acc = 0.f;
        const int rsB = t >> 7;         // which of the 4 staged rows
        const int seg = t & 127;        // 4-column run: cols [seg*4, seg*4+4)
        const float inv81 = 1.0f / 81.0f;

        // phase B: horizontal 9-sums + cc for buffer `buf`
        auto phaseB = [&](int buf) {
            float S[5][4];
#pragma unroll
            for (int q = 0; q < 5; q++) {
                const float4* row4 =
                    (const float4*)(stage + (size_t)((buf * RB + rsB) * 5 + q) * ROWF);
                float4 A = row4[seg], B = row4[seg + 1], C = row4[seg + 2];
                float s = A.x + A.y + A.z + A.w + B.x + B.y + B.z + B.w + C.x;
                S[q][0] = s;
                s += C.y - A.x; S[q][1] = s;
                s += C.z - A.y; S[q][2] = s;
                s += C.w - A.z; S[q][3] = s;
            }
#pragma unroll
            for (int i = 0; i < 4; i++) {
                float sI = S[0][i], sJ = S[1][i];
                float sII = S[2][i], sJJ = S[3][i], sIJ = S[4][i];
                float cross = sIJ - sI * sJ * inv81;
                float Iv = sII - sI * sI * inv81;
                float Jv = sJJ - sJ * sJ * inv81;
                acc += __fdividef(cross * cross, Iv * Jv + 1e-5f);
            }
        };

        __syncthreads();                // padding visible
        phaseA(0, r0, 0);               // batch 0 (jpar = 0)
        __syncthreads();                // buf0 ready

#pragma unroll 2
        for (int b = 0; b < NBATCH; b++) {
            if (b + 1 < NBATCH)
                phaseA((b + 1) & 1, r0 + (b + 1) * RB, (b + 1) & 1);  // overlaps B(b)
            phaseB(b & 1);
            __syncthreads();            // publishes A(b+1), protects buf reuse
        }

        // block reduction
#pragma unroll
        for (int d = 16; d > 0; d >>= 1) acc += __shfl_down_sync(0xffffffffu, acc, d);
        if ((t & 31) == 0) red[t >> 5] = acc;
        __syncthreads();
        if (t < 32) {
            float v = (t < 16) ? red[t] : 0.f;
#pragma unroll
            for (int d = 8; d > 0; d >>= 1) v += __shfl_down_sync(0xffffffffu, v, d);
            if (t == 0) atomicAdd(&g_acc[img & 1], (double)v);
        }
    } else {
        // ───────────────────────── grad block ─────────────────────────
        float adx = 0.f, ady = 0.f;
        const int gb = blk - NCC_BLOCKS;
        for (int idx = gb * 512 + t; idx < n_dvf; idx += GRAD_BLOCKS * 512) {
            const int hw = idx & 65535;          // position within one 256x256 map
            const float c = dvf[idx];
            if ((hw & 255) != 255) { float d = dvf[idx + 1] - c; adx += d * d; }
            if (hw < 65280)        { float d = dvf[idx + 256] - c; ady += d * d; }
        }
#pragma unroll
        for (int d = 16; d > 0; d >>= 1) {
            adx += __shfl_down_sync(0xffffffffu, adx, d);
            ady += __shfl_down_sync(0xffffffffu, ady, d);
        }
        if ((t & 31) == 0) { red[t >> 5] = adx; red2[t >> 5] = ady; }
        __syncthreads();
        if (t < 32) {
            float x = (t < 16) ? red[t] : 0.f;
            float y = (t < 16) ? red2[t] : 0.f;
#pragma unroll
            for (int d = 8; d > 0; d >>= 1) {
                x += __shfl_down_sync(0xffffffffu, x, d);
                y += __shfl_down_sync(0xffffffffu, y, d);
            }
            if (t == 0) {
                atomicAdd(&g_acc[2], (double)x);
                atomicAdd(&g_acc[3], (double)y);
            }
        }
    }

    // ───────────────── last-block finalize (graph-replay safe) ─────────────────
    __threadfence();
    if (t == 0) {
        unsigned int prev = atomicAdd(&g_count, 1u);
        is_last = (prev == (unsigned int)(TOTAL_BLOCKS - 1));
    }
    __syncthreads();
    if (is_last && t == 0) {
        // ncc = -(m0 + m1)/(C-1), C=2; m_c = sum_c / (B*H*W)
        double ncc = -(g_acc[0] + g_acc[1]) / (16.0 * 512.0 * 512.0);
        // grad = 0.01 * ((mean(dx^2)+mean(dy^2))/2 * 2.0)
        double Nd = 16.0 * 2.0 * 256.0 * 255.0;
        double grad = 0.01 * (g_acc[2] / Nd + g_acc[3] / Nd);
        out[0] = (float)(ncc + grad);
        out[1] = (float)ncc;
        out[2] = (float)grad;
        g_acc[0] = 0.0; g_acc[1] = 0.0; g_acc[2] = 0.0; g_acc[3] = 0.0;
        g_count = 0u;
    }
}

extern "C" void kernel_launch(void* const* d_in, const int* in_sizes, int n_in,
                              void* d_out, int out_size) {
    const float* y_true = (const float*)d_in[0];
    const float* y_pred = (const float*)d_in[1];
    const float* dvf    = (const float*)d_in[2];
    float* out = (float*)d_out;
    const int n_dvf = in_sizes[2];

    cudaFuncSetAttribute(fused_kernel, cudaFuncAttributeMaxDynamicSharedMemorySize,
                         SMEM_BYTES);
    cudaFuncSetAttribute(fused_kernel, cudaFuncAttributePreferredSharedMemoryCarveout,
                         100);   // max carveout so two 116KB blocks co-reside
    fused_kernel<<<TOTAL_BLOCKS, 512, SMEM_BYTES>>>(y_true, y_pred, dvf, n_dvf, out);
}

// round 8
// speedup vs baseline: 1.1445x; 1.1370x over previous
#include <cuda_runtime.h>

#define WD 512
#define RB 4
#define NBATCH 8
#define ROWF 512            // no pads; boundary handled by predicated zeros
#define NCC_BLOCKS 512
#define GRAD_BLOCKS 64
#define TOTAL_BLOCKS (NCC_BLOCKS + GRAD_BLOCKS)
#define STAGE_FLOATS (2 * RB * 5 * ROWF)       // 20480 floats = 81920 B (double buffer)
#define STASH_FLOATS (8 * WD * 2)              // 8192 floats = 32768 B (8-row raw ring)
#define SMEM_BYTES ((STAGE_FLOATS + STASH_FLOATS) * 4)   // 114688 B

// [0],[1]: cc sums per channel; [2]: sum dx^2; [3]: sum dy^2
__device__ double g_acc[4];
__device__ unsigned int g_count;

__global__ __launch_bounds__(512, 2) void fused_kernel(const float* __restrict__ I,
                                                       const float* __restrict__ J,
                                                       const float* __restrict__ dvf,
                                                       int n_dvf,
                                                       float* __restrict__ out) {
    extern __shared__ __align__(16) float dyn[];
    float* stage = dyn;                              // [2][RB][5][ROWF]
    float2* stash = (float2*)(dyn + STAGE_FLOATS);   // [8][WD] float2 (a,b)
    __shared__ float red[16];
    __shared__ float red2[16];
    __shared__ bool is_last;

    const int t = threadIdx.x;
    const int blk = blockIdx.x;

    if (blk < NCC_BLOCKS) {
        // ───────────────────────── NCC block ─────────────────────────
        const int img = blk >> 4;       // 16 bands per image, 32 images
        const int band = blk & 15;
        const int r0 = band * 32;       // multiple of 32 -> r0 & 7 == 0
        const size_t base = (size_t)img * (WD * WD);
        const float* __restrict__ Ip = I + base;
        const float* __restrict__ Jp = J + base;

        // prime: column sums over rows [r0-4, r0+3]; stash raw rows in ring.
        // slot(row x) = x & 7; r0 ≡ 0 (mod 8) so slot = (k+4)&7 here.
        float cs0 = 0.f, cs1 = 0.f, cs2 = 0.f, cs3 = 0.f, cs4 = 0.f;
#pragma unroll
        for (int k = 0; k < 8; k++) {
            const int r = r0 - 4 + k;
            float a = 0.f, b = 0.f;
            if (r >= 0) { a = Ip[r * WD + t]; b = Jp[r * WD + t]; }
            stash[((k + 4) & 7) * WD + t] = make_float2(a, b);
            cs0 += a; cs1 += b; cs2 += a * a; cs3 += b * b; cs4 += a * b;
        }

        // phase A: slide vertical sums over RB rows, stage column sums.
        // jpar = (rbase/4) & 1 — makes stash slots compile-time constants.
        auto phaseA = [&](int buf, int rbase, int jpar) {
#pragma unroll
            for (int rr = 0; rr < RB; rr++) {
                const int r = rbase + rr;
                const int slot = (jpar * 4 + rr + 4) & 7;   // == (r+4)&7 == (r-4)&7
                // read sub row (r-4) from stash BEFORE overwriting the slot
                float2 cd = stash[slot * WD + t];
                // load add row (r+4) from global (each row read exactly once)
                float a = 0.f, b = 0.f;
                if (r + 4 < WD) { a = Ip[(r + 4) * WD + t]; b = Jp[(r + 4) * WD + t]; }
                stash[slot * WD + t] = make_float2(a, b);
                cs0 += a; cs1 += b; cs2 += a * a; cs3 += b * b; cs4 += a * b;
                float* rowp = stage + (size_t)((buf * RB + rr) * 5) * ROWF + t;
                rowp[0 * ROWF] = cs0;
                rowp[1 * ROWF] = cs1;
                rowp[2 * ROWF] = cs2;
                rowp[3 * ROWF] = cs3;
                rowp[4 * ROWF] = cs4;
                cs0 -= cd.x; cs1 -= cd.y;
                cs2 -= cd.x * cd.x; cs3 -= cd.y * cd.y; cs4 -= cd.x * cd.y;
            }
        };

        float acc = 0.f;
        const int rsB = t >> 7;         // which of the 4 staged rows
        const int seg = t & 127;        // 4-column run: cols [seg*4, seg*4+4)
        const float inv81 = 1.0f / 81.0f;
        const bool hasL = (seg > 0);
        const bool hasR = (seg < 127);

        // phase B: horizontal 9-sums + cc for buffer `buf`.
        // window [c-4, c+7] = float4 blocks seg-1, seg, seg+1; out-of-range
        // blocks are exactly zero (zero-padded convolution) -> predicated zeros.
        auto phaseB = [&](int buf) {
            float S[5][4];
#pragma unroll
            for (int q = 0; q < 5; q++) {
                const float4* row4 =
                    (const float4*)(stage + (size_t)((buf * RB + rsB) * 5 + q) * ROWF);
                float4 A = hasL ? row4[seg - 1] : make_float4(0.f, 0.f, 0.f, 0.f);
                float4 B = row4[seg];
                float4 C = hasR ? row4[seg + 1] : make_float4(0.f, 0.f, 0.f, 0.f);
                float s = A.x + A.y + A.z + A.w + B.x + B.y + B.z + B.w + C.x;
                S[q][0] = s;
                s += C.y - A.x; S[q][1] = s;
                s += C.z - A.y; S[q][2] = s;
                s += C.w - A.z; S[q][3] = s;
            }
#pragma unroll
            for (int i = 0; i < 4; i++) {
                float sI = S[0][i], sJ = S[1][i];
                float sII = S[2][i], sJJ = S[3][i], sIJ = S[4][i];
                float cross = sIJ - sI * sJ * inv81;
                float Iv = sII - sI * sI * inv81;
                float Jv = sJJ - sJ * sJ * inv81;
                acc += __fdividef(cross * cross, Iv * Jv + 1e-5f);
            }
        };

        phaseA(0, r0, 0);               // batch 0 (jpar = 0)
        __syncthreads();                // buf0 ready

#pragma unroll 2
        for (int b = 0; b < NBATCH; b++) {
            if (b + 1 < NBATCH)
                phaseA((b + 1) & 1, r0 + (b + 1) * RB, (b + 1) & 1);  // overlaps B(b)
            phaseB(b & 1);
            __syncthreads();            // publishes A(b+1), protects buf reuse
        }

        // block reduction
#pragma unroll
        for (int d = 16; d > 0; d >>= 1) acc += __shfl_down_sync(0xffffffffu, acc, d);
        if ((t & 31) == 0) red[t >> 5] = acc;
        __syncthreads();
        if (t < 32) {
            float v = (t < 16) ? red[t] : 0.f;
#pragma unroll
            for (int d = 8; d > 0; d >>= 1) v += __shfl_down_sync(0xffffffffu, v, d);
            if (t == 0) atomicAdd(&g_acc[img & 1], (double)v);
        }
    } else {
        // ───────────────────────── grad block ─────────────────────────
        float adx = 0.f, ady = 0.f;
        const int gb = blk - NCC_BLOCKS;
        for (int idx = gb * 512 + t; idx < n_dvf; idx += GRAD_BLOCKS * 512) {
            const int hw = idx & 65535;          // position within one 256x256 map
            const float c = dvf[idx];
            if ((hw & 255) != 255) { float d = dvf[idx + 1] - c; adx += d * d; }
            if (hw < 65280)        { float d = dvf[idx + 256] - c; ady += d * d; }
        }
#pragma unroll
        for (int d = 16; d > 0; d >>= 1) {
            adx += __shfl_down_sync(0xffffffffu, adx, d);
            ady += __shfl_down_sync(0xffffffffu, ady, d);
        }
        if ((t & 31) == 0) { red[t >> 5] = adx; red2[t >> 5] = ady; }
        __syncthreads();
        if (t < 32) {
            float x = (t < 16) ? red[t] : 0.f;
            float y = (t < 16) ? red2[t] : 0.f;
#pragma unroll
            for (int d = 8; d > 0; d >>= 1) {
                x += __shfl_down_sync(0xffffffffu, x, d);
                y += __shfl_down_sync(0xffffffffu, y, d);
            }
            if (t == 0) {
                atomicAdd(&g_acc[2], (double)x);
                atomicAdd(&g_acc[3], (double)y);
            }
        }
    }

    // ───────────────── last-block finalize (graph-replay safe) ─────────────────
    __threadfence();
    if (t == 0) {
        unsigned int prev = atomicAdd(&g_count, 1u);
        is_last = (prev == (unsigned int)(TOTAL_BLOCKS - 1));
    }
    __syncthreads();
    if (is_last && t == 0) {
        // ncc = -(m0 + m1)/(C-1), C=2; m_c = sum_c / (B*H*W)
        double ncc = -(g_acc[0] + g_acc[1]) / (16.0 * 512.0 * 512.0);
        // grad = 0.01 * ((mean(dx^2)+mean(dy^2))/2 * 2.0)
        double Nd = 16.0 * 2.0 * 256.0 * 255.0;
        double grad = 0.01 * (g_acc[2] / Nd + g_acc[3] / Nd);
        out[0] = (float)(ncc + grad);
        out[1] = (float)ncc;
        out[2] = (float)grad;
        g_acc[0] = 0.0; g_acc[1] = 0.0; g_acc[2] = 0.0; g_acc[3] = 0.0;
        g_count = 0u;
    }
}

extern "C" void kernel_launch(void* const* d_in, const int* in_sizes, int n_in,
                              void* d_out, int out_size) {
    const float* y_true = (const float*)d_in[0];
    const float* y_pred = (const float*)d_in[1];
    const float* dvf    = (const float*)d_in[2];
    float* out = (float*)d_out;
    const int n_dvf = in_sizes[2];

    cudaFuncSetAttribute(fused_kernel, cudaFuncAttributeMaxDynamicSharedMemorySize,
                         SMEM_BYTES);
    cudaFuncSetAttribute(fused_kernel, cudaFuncAttributePreferredSharedMemoryCarveout,
                         100);   // max carveout so two blocks co-reside
    fused_kernel<<<TOTAL_BLOCKS, 512, SMEM_BYTES>>>(y_true, y_pred, dvf, n_dvf, out);
}